// round 1
// baseline (speedup 1.0000x reference)
#include <cuda_runtime.h>

#define NVOX  150000
#define CIN   32
#define COUT  64
#define NK    27
#define TILE  256
#define THREADS 512
#define GROUPS  8            // THREADS / COUT
#define RPT     (TILE/GROUPS) // 32 rows per thread

__device__ float g_stats[2*COUT];   // [0:64) sum, [64:128) sumsq
__device__ float g_scale[COUT];
__device__ float g_shift[COUT];

__global__ void zero_stats_kernel() {
    int t = threadIdx.x;
    if (t < 2*COUT) g_stats[t] = 0.f;
}

__global__ __launch_bounds__(THREADS, 1)
void conv_kernel(const float* __restrict__ features,
                 const float* __restrict__ weight,
                 const int*   __restrict__ nbr,
                 float* __restrict__ out)
{
    __shared__ float sW[CIN*COUT];      // 8 KB, W_k as [c][d]
    __shared__ float sF[TILE][CIN];     // 32 KB, gathered features
    __shared__ int   sIdx[TILE];        // 1 KB

    const int t  = threadIdx.x;
    const int d  = t & (COUT-1);
    const int g  = t >> 6;              // 0..7
    const int n0 = blockIdx.x * TILE;

    float acc[RPT];
    #pragma unroll
    for (int i = 0; i < RPT; i++) acc[i] = 0.f;

    for (int k = 0; k < NK; k++) {
        __syncthreads();  // protect smem reuse from previous iteration's compute

        // stage neighbor indices for this offset
        if (t < TILE) {
            int n = n0 + t;
            sIdx[t] = (n < NVOX) ? nbr[k*NVOX + n] : -1;
        }
        // stage W_k: 2048 floats, 512 threads x 1 float4
        ((float4*)sW)[t] = ((const float4*)(weight + k*CIN*COUT))[t];
        __syncthreads();

        // gather features for valid rows: 2 threads per row, 4 float4 each
        {
            int r    = t >> 1;
            int half = t & 1;
            int idx  = sIdx[r];
            if (idx >= 0) {
                const float4* src = ((const float4*)(features + (long long)idx*CIN)) + half*4;
                float4* dst = ((float4*)(&sF[r][0])) + half*4;
                dst[0] = src[0]; dst[1] = src[1]; dst[2] = src[2]; dst[3] = src[3];
            }
        }
        __syncthreads();

        // compute: c in chunks of 8 (keeps live regs low), rows branch-skipped
        #pragma unroll
        for (int c0 = 0; c0 < CIN; c0 += 8) {
            float w[8];
            #pragma unroll
            for (int j = 0; j < 8; j++) w[j] = sW[(c0+j)*COUT + d];

            #pragma unroll
            for (int i = 0; i < RPT; i++) {
                int r = g + i*GROUPS;
                if (sIdx[r] >= 0) {
                    const float4* fr = (const float4*)(&sF[r][c0]);
                    float4 fa = fr[0];
                    float4 fb = fr[1];
                    float a = acc[i];
                    a = fmaf(fa.x, w[0], a);
                    a = fmaf(fa.y, w[1], a);
                    a = fmaf(fa.z, w[2], a);
                    a = fmaf(fa.w, w[3], a);
                    a = fmaf(fb.x, w[4], a);
                    a = fmaf(fb.y, w[5], a);
                    a = fmaf(fb.z, w[6], a);
                    a = fmaf(fb.w, w[7], a);
                    acc[i] = a;
                }
            }
        }
    }

    // write conv output (pre-BN) into d_out as scratch
    #pragma unroll
    for (int i = 0; i < RPT; i++) {
        int n = n0 + g + i*GROUPS;
        if (n < NVOX) out[n*COUT + d] = acc[i];
    }

    // per-thread partial stats, then block reduce over the 8 groups per channel
    float s = 0.f, q = 0.f;
    #pragma unroll
    for (int i = 0; i < RPT; i++) { s += acc[i]; q = fmaf(acc[i], acc[i], q); }

    __syncthreads();
    float* red = (float*)sF;            // reuse 32 KB smem
    red[t]           = s;
    red[THREADS + t] = q;
    __syncthreads();

    if (t < COUT) {
        float S = 0.f, Q = 0.f;
        #pragma unroll
        for (int gg = 0; gg < GROUPS; gg++) {
            S += red[gg*COUT + t];
            Q += red[THREADS + gg*COUT + t];
        }
        atomicAdd(&g_stats[t],        S);
        atomicAdd(&g_stats[COUT + t], Q);
    }
}

__global__ void finalize_kernel(const float* __restrict__ gamma,
                                const float* __restrict__ beta)
{
    int d = threadIdx.x;
    if (d < COUT) {
        float inv_n = 1.0f / (float)NVOX;
        float mean  = g_stats[d] * inv_n;
        float var   = g_stats[COUT + d] * inv_n - mean*mean;
        float inv   = rsqrtf(var + 1e-5f);
        float sc    = gamma[d] * inv;
        g_scale[d]  = sc;
        g_shift[d]  = beta[d] - mean*sc;
    }
}

__global__ void norm_kernel(float* __restrict__ out)
{
    __shared__ float sc[COUT], sh[COUT];
    int t = threadIdx.x;
    if (t < COUT) { sc[t] = g_scale[t]; sh[t] = g_shift[t]; }
    __syncthreads();

    const int total4 = NVOX*COUT/4;   // 2,400,000
    float4* o4 = (float4*)out;
    for (int i = blockIdx.x*blockDim.x + t; i < total4; i += gridDim.x*blockDim.x) {
        float4 v = o4[i];
        int bd = (i*4) & (COUT-1);
        v.x = fmaxf(fmaf(v.x, sc[bd+0], sh[bd+0]), 0.f);
        v.y = fmaxf(fmaf(v.y, sc[bd+1], sh[bd+1]), 0.f);
        v.z = fmaxf(fmaf(v.z, sc[bd+2], sh[bd+2]), 0.f);
        v.w = fmaxf(fmaf(v.w, sc[bd+3], sh[bd+3]), 0.f);
        o4[i] = v;
    }
}

extern "C" void kernel_launch(void* const* d_in, const int* in_sizes, int n_in,
                              void* d_out, int out_size)
{
    const float* features = (const float*)d_in[0];  // [150000,32]
    const float* weight   = (const float*)d_in[1];  // [27,32,64]
    const float* gamma    = (const float*)d_in[2];  // [64]
    const float* beta     = (const float*)d_in[3];  // [64]
    const int*   nbr      = (const int*)  d_in[4];  // [27,150000]
    float* out = (float*)d_out;                     // [150000,64]

    zero_stats_kernel<<<1, 128>>>();
    conv_kernel<<<(NVOX + TILE - 1)/TILE, THREADS>>>(features, weight, nbr, out);
    finalize_kernel<<<1, COUT>>>(gamma, beta);
    norm_kernel<<<1480, 256>>>(out);
}

// round 2
// speedup vs baseline: 3.6299x; 3.6299x over previous
#include <cuda_runtime.h>

#define NVOX    150000
#define CIN     32
#define COUT    64
#define NK      27
#define KCENTER 13

__device__ float g_stats[2*COUT];   // [0:64) sum, [64:128) sumsq
__device__ float g_scale[COUT];
__device__ float g_shift[COUT];
__device__ int   g_count;
__device__ int2  g_list[26*NVOX];   // worst-case rulebook (actual ~35K entries)

// ---------------------------------------------------------------- zero
__global__ void zero_kernel() {
    int t = threadIdx.x;
    if (t < 2*COUT) g_stats[t] = 0.f;
    if (t == 0)     g_count = 0;
}

// ---------------------------------------------------------------- compact
// Scan the 26 non-center offsets, append valid (k,n,idx) entries.
__global__ __launch_bounds__(256)
void compact_kernel(const int* __restrict__ nbr) {
    int kp = blockIdx.y;                 // 0..25
    int k  = kp + (kp >= KCENTER);       // skip center
    int n  = blockIdx.x * blockDim.x + threadIdx.x;
    int v  = -1;
    if (n < NVOX) v = nbr[k*NVOX + n];
    bool valid = (v >= 0);

    unsigned mask = __ballot_sync(0xffffffffu, valid);
    if (mask) {
        int lane   = threadIdx.x & 31;
        int leader = __ffs(mask) - 1;
        int base   = 0;
        if (lane == leader) base = atomicAdd(&g_count, __popc(mask));
        base = __shfl_sync(0xffffffffu, base, leader);
        if (valid) {
            int pos = base + __popc(mask & ((1u << lane) - 1));
            g_list[pos] = make_int2(n | (k << 20), v);
        }
    }
}

// ---------------------------------------------------------------- center GEMM
// out[n,:] = features[nbr[13,n],:] @ W[13]   (center offset, always valid)
__global__ __launch_bounds__(256)
void center_gemm_kernel(const float* __restrict__ features,
                        const float* __restrict__ weight,
                        const int*   __restrict__ nbr,
                        float* __restrict__ out)
{
    const int lane = threadIdx.x & 31;
    const int warp = threadIdx.x >> 5;
    const int d0   = lane * 2;

    // weights for the center offset: 32 x float2 in registers (L1-hot loads)
    float2 w[CIN];
    const float* wk = weight + KCENTER*CIN*COUT;
    #pragma unroll
    for (int c = 0; c < CIN; c++)
        w[c] = *(const float2*)(wk + c*COUT + d0);

    const int nwarps = (gridDim.x * blockDim.x) >> 5;
    for (int n = (blockIdx.x * blockDim.x >> 5) + warp; n < NVOX; n += nwarps) {
        int idx = __ldg(&nbr[KCENTER*NVOX + n]);
        float acc0 = 0.f, acc1 = 0.f;
        if (idx >= 0) {
            const float4* f4 = (const float4*)(features + (size_t)idx * CIN);
            #pragma unroll
            for (int j = 0; j < 8; j++) {
                float4 v = f4[j];   // same addr across warp -> broadcast
                acc0 = fmaf(v.x, w[4*j+0].x, acc0); acc1 = fmaf(v.x, w[4*j+0].y, acc1);
                acc0 = fmaf(v.y, w[4*j+1].x, acc0); acc1 = fmaf(v.y, w[4*j+1].y, acc1);
                acc0 = fmaf(v.z, w[4*j+2].x, acc0); acc1 = fmaf(v.z, w[4*j+2].y, acc1);
                acc0 = fmaf(v.w, w[4*j+3].x, acc0); acc1 = fmaf(v.w, w[4*j+3].y, acc1);
            }
        }
        *(float2*)(out + (size_t)n*COUT + d0) = make_float2(acc0, acc1);
    }
}

// ---------------------------------------------------------------- scatter
// One warp per rulebook entry: out[n,:] += features[idx,:] @ W[k]
__global__ __launch_bounds__(256)
void scatter_kernel(const float* __restrict__ features,
                    const float* __restrict__ weight,
                    float* __restrict__ out)
{
    const int lane  = threadIdx.x & 31;
    const int wid   = (blockIdx.x * blockDim.x + threadIdx.x) >> 5;
    const int nw    = (gridDim.x * blockDim.x) >> 5;
    const int total = g_count;
    const int d0    = lane * 2;

    for (int e = wid; e < total; e += nw) {
        int2 ent = g_list[e];
        int n    = ent.x & 0xFFFFF;
        int k    = ent.x >> 20;
        int idx  = ent.y;

        float fc = features[(size_t)idx*CIN + lane];   // coalesced 128B row
        const float* wk = weight + k*CIN*COUT;

        float acc0 = 0.f, acc1 = 0.f;
        #pragma unroll
        for (int c = 0; c < CIN; c++) {
            float  f  = __shfl_sync(0xffffffffu, fc, c);
            float2 wv = *(const float2*)(wk + c*COUT + d0);  // L2-hot
            acc0 = fmaf(f, wv.x, acc0);
            acc1 = fmaf(f, wv.y, acc1);
        }
        atomicAdd(out + (size_t)n*COUT + d0,     acc0);
        atomicAdd(out + (size_t)n*COUT + d0 + 1, acc1);
    }
}

// ---------------------------------------------------------------- stats
__global__ __launch_bounds__(256)
void stats_kernel(const float* __restrict__ out)
{
    __shared__ float4 ss[256], qq[256];
    const int t  = threadIdx.x;
    const int c4 = t & 15;       // float4 column (channels 4*c4 .. 4*c4+3)
    const int rl = t >> 4;       // 0..15 row lane

    float4 s = make_float4(0,0,0,0), q = make_float4(0,0,0,0);
    const float4* o4 = (const float4*)out;
    for (int r = blockIdx.x*16 + rl; r < NVOX; r += gridDim.x*16) {
        float4 v = o4[(size_t)r*16 + c4];
        s.x += v.x; s.y += v.y; s.z += v.z; s.w += v.w;
        q.x = fmaf(v.x, v.x, q.x); q.y = fmaf(v.y, v.y, q.y);
        q.z = fmaf(v.z, v.z, q.z); q.w = fmaf(v.w, v.w, q.w);
    }
    ss[t] = s; qq[t] = q;
    __syncthreads();

    if (t < 16) {
        float4 S = make_float4(0,0,0,0), Q = make_float4(0,0,0,0);
        #pragma unroll
        for (int j = 0; j < 16; j++) {
            float4 a = ss[j*16 + t];
            float4 b = qq[j*16 + t];
            S.x += a.x; S.y += a.y; S.z += a.z; S.w += a.w;
            Q.x += b.x; Q.y += b.y; Q.z += b.z; Q.w += b.w;
        }
        atomicAdd(&g_stats[t*4+0], S.x); atomicAdd(&g_stats[t*4+1], S.y);
        atomicAdd(&g_stats[t*4+2], S.z); atomicAdd(&g_stats[t*4+3], S.w);
        atomicAdd(&g_stats[COUT + t*4+0], Q.x); atomicAdd(&g_stats[COUT + t*4+1], Q.y);
        atomicAdd(&g_stats[COUT + t*4+2], Q.z); atomicAdd(&g_stats[COUT + t*4+3], Q.w);
    }
}

// ---------------------------------------------------------------- finalize
__global__ void finalize_kernel(const float* __restrict__ gamma,
                                const float* __restrict__ beta)
{
    int d = threadIdx.x;
    if (d < COUT) {
        float inv_n = 1.0f / (float)NVOX;
        float mean  = g_stats[d] * inv_n;
        float var   = g_stats[COUT + d] * inv_n - mean*mean;
        float inv   = rsqrtf(var + 1e-5f);
        float sc    = gamma[d] * inv;
        g_scale[d]  = sc;
        g_shift[d]  = beta[d] - mean*sc;
    }
}

// ---------------------------------------------------------------- normalize
__global__ __launch_bounds__(256)
void norm_kernel(float* __restrict__ out)
{
    __shared__ float sc[COUT], sh[COUT];
    int t = threadIdx.x;
    if (t < COUT) { sc[t] = g_scale[t]; sh[t] = g_shift[t]; }
    __syncthreads();

    const int total4 = NVOX*COUT/4;
    float4* o4 = (float4*)out;
    for (int i = blockIdx.x*blockDim.x + t; i < total4; i += gridDim.x*blockDim.x) {
        float4 v = o4[i];
        int bd = (i*4) & (COUT-1);
        v.x = fmaxf(fmaf(v.x, sc[bd+0], sh[bd+0]), 0.f);
        v.y = fmaxf(fmaf(v.y, sc[bd+1], sh[bd+1]), 0.f);
        v.z = fmaxf(fmaf(v.z, sc[bd+2], sh[bd+2]), 0.f);
        v.w = fmaxf(fmaf(v.w, sc[bd+3], sh[bd+3]), 0.f);
        o4[i] = v;
    }
}

// ---------------------------------------------------------------- launch
extern "C" void kernel_launch(void* const* d_in, const int* in_sizes, int n_in,
                              void* d_out, int out_size)
{
    const float* features = (const float*)d_in[0];  // [150000,32]
    const float* weight   = (const float*)d_in[1];  // [27,32,64]
    const float* gamma    = (const float*)d_in[2];  // [64]
    const float* beta     = (const float*)d_in[3];  // [64]
    const int*   nbr      = (const int*)  d_in[4];  // [27,150000]
    float* out = (float*)d_out;                     // [150000,64]

    zero_kernel<<<1, 128>>>();
    compact_kernel<<<dim3((NVOX + 255)/256, 26), 256>>>(nbr);
    center_gemm_kernel<<<1184, 256>>>(features, weight, nbr, out);
    scatter_kernel<<<296, 256>>>(features, weight, out);
    stats_kernel<<<592, 256>>>(out);
    finalize_kernel<<<1, COUT>>>(gamma, beta);
    norm_kernel<<<1480, 256>>>(out);
}

// round 3
// speedup vs baseline: 4.1266x; 1.1368x over previous
#include <cuda_runtime.h>

#define NVOX    150000
#define CIN     32
#define COUT    64
#define KCENTER 13
#define CAP     16384          // per-offset rulebook capacity (expected ~1350)

__device__ float g_stats[2*COUT];   // [0:64) sum, [64:128) sumsq
__device__ float g_scale[COUT];
__device__ float g_shift[COUT];
__device__ int   g_cnt[26];
__device__ int2  g_list[26*CAP];    // per-k compacted (n, idx) entries

// ---------------------------------------------------------------- f32x2 helpers
__device__ __forceinline__ unsigned long long dup2(float x) {
    unsigned long long r; asm("mov.b64 %0, {%1, %1};" : "=l"(r) : "f"(x)); return r;
}
__device__ __forceinline__ unsigned long long pack2(float x, float y) {
    unsigned long long r; asm("mov.b64 %0, {%1, %2};" : "=l"(r) : "f"(x), "f"(y)); return r;
}
__device__ __forceinline__ void unpack2(unsigned long long v, float& x, float& y) {
    asm("mov.b64 {%0, %1}, %2;" : "=f"(x), "=f"(y) : "l"(v));
}
__device__ __forceinline__ void ffma2(unsigned long long& acc,
                                      unsigned long long a, unsigned long long b) {
    asm("fma.rn.f32x2 %0, %1, %2, %0;" : "+l"(acc) : "l"(a), "l"(b));
}
__device__ __forceinline__ unsigned long long add2(unsigned long long a, unsigned long long b) {
    unsigned long long r; asm("add.rn.f32x2 %0, %1, %2;" : "=l"(r) : "l"(a), "l"(b)); return r;
}

// ---------------------------------------------------------------- zero
__global__ void zero_kernel() {
    int t = threadIdx.x;
    if (t < 2*COUT) g_stats[t] = 0.f;
    if (t < 26)     g_cnt[t] = 0;
}

// ---------------------------------------------------------------- compact (26 non-center offsets)
__global__ __launch_bounds__(256)
void compact_kernel(const int* __restrict__ nbr) {
    int kp = blockIdx.y;                 // 0..25
    int k  = kp + (kp >= KCENTER);       // actual offset, skipping center
    int n  = blockIdx.x * blockDim.x + threadIdx.x;
    int v  = -1;
    if (n < NVOX) v = nbr[k*NVOX + n];
    bool valid = (v >= 0);

    unsigned mask = __ballot_sync(0xffffffffu, valid);
    if (mask) {
        int lane   = threadIdx.x & 31;
        int leader = __ffs(mask) - 1;
        int base   = 0;
        if (lane == leader) base = atomicAdd(&g_cnt[kp], __popc(mask));
        base = __shfl_sync(0xffffffffu, base, leader);
        if (valid) {
            int pos = base + __popc(mask & ((1u << lane) - 1));
            if (pos < CAP) g_list[kp*CAP + pos] = make_int2(n, v);
        }
    }
}

// ---------------------------------------------------------------- center GEMM (k=13: idx == n)
__global__ __launch_bounds__(256)
void center_gemm_kernel(const float* __restrict__ features,
                        const float* __restrict__ weight,
                        float* __restrict__ out)
{
    const int lane = threadIdx.x & 31;
    const int warp = threadIdx.x >> 5;
    const int d0   = lane * 2;

    // W13[c][d0:d0+2] packed into 32 u64 registers
    unsigned long long w[CIN];
    const float* wk = weight + KCENTER*CIN*COUT;
    #pragma unroll
    for (int c = 0; c < CIN; c++) {
        float2 wv = *(const float2*)(wk + c*COUT + d0);
        w[c] = pack2(wv.x, wv.y);
    }

    const int nwarps = (gridDim.x * blockDim.x) >> 5;
    for (int n = ((blockIdx.x * blockDim.x) >> 5) + warp; n < NVOX; n += nwarps) {
        const float4* f4 = (const float4*)(features + (size_t)n * CIN);
        unsigned long long accA = 0, accB = 0;   // two chains (packed zero == 0.0f pair)
        #pragma unroll
        for (int j = 0; j < 8; j++) {
            float4 v = f4[j];        // same addr across warp -> broadcast
            ffma2(accA, dup2(v.x), w[4*j+0]);
            ffma2(accB, dup2(v.y), w[4*j+1]);
            ffma2(accA, dup2(v.z), w[4*j+2]);
            ffma2(accB, dup2(v.w), w[4*j+3]);
        }
        unsigned long long acc = add2(accA, accB);
        float a0, a1; unpack2(acc, a0, a1);
        *(float2*)(out + (size_t)n*COUT + d0) = make_float2(a0, a1);
    }
}

// ---------------------------------------------------------------- scatter (k-specialized)
__global__ __launch_bounds__(256)
void scatter_kernel(const float* __restrict__ features,
                    const float* __restrict__ weight,
                    float* __restrict__ out)
{
    const int kp   = blockIdx.y;                 // 0..25
    const int k    = kp + (kp >= KCENTER);
    const int lane = threadIdx.x & 31;
    const int warp = threadIdx.x >> 5;
    const int d0   = lane * 2;

    const int total = g_cnt[kp];
    const int wid   = blockIdx.x * (blockDim.x >> 5) + warp;
    const int nw    = gridDim.x * (blockDim.x >> 5);
    if (wid >= total) return;

    // W_k[c][d0:d0+2] in registers, loaded once per warp
    unsigned long long w[CIN];
    const float* wk = weight + k*CIN*COUT;
    #pragma unroll
    for (int c = 0; c < CIN; c++) {
        float2 wv = *(const float2*)(wk + c*COUT + d0);
        w[c] = pack2(wv.x, wv.y);
    }

    for (int e = wid; e < total; e += nw) {
        int2 ent = g_list[kp*CAP + e];
        const float4* f4 = (const float4*)(features + (size_t)ent.y * CIN);
        unsigned long long accA = 0, accB = 0;
        #pragma unroll
        for (int j = 0; j < 8; j++) {
            float4 v = f4[j];
            ffma2(accA, dup2(v.x), w[4*j+0]);
            ffma2(accB, dup2(v.y), w[4*j+1]);
            ffma2(accA, dup2(v.z), w[4*j+2]);
            ffma2(accB, dup2(v.w), w[4*j+3]);
        }
        unsigned long long acc = add2(accA, accB);
        float a0, a1; unpack2(acc, a0, a1);
        asm volatile("red.global.add.v2.f32 [%0], {%1, %2};"
                     :: "l"(out + (size_t)ent.x*COUT + d0), "f"(a0), "f"(a1) : "memory");
    }
}

// ---------------------------------------------------------------- stats
__global__ __launch_bounds__(256)
void stats_kernel(const float* __restrict__ out)
{
    __shared__ float4 ss[256], qq[256];
    const int t  = threadIdx.x;
    const int c4 = t & 15;
    const int rl = t >> 4;

    float4 s = make_float4(0,0,0,0), q = make_float4(0,0,0,0);
    const float4* o4 = (const float4*)out;
    for (int r = blockIdx.x*16 + rl; r < NVOX; r += gridDim.x*16) {
        float4 v = o4[(size_t)r*16 + c4];
        s.x += v.x; s.y += v.y; s.z += v.z; s.w += v.w;
        q.x = fmaf(v.x, v.x, q.x); q.y = fmaf(v.y, v.y, q.y);
        q.z = fmaf(v.z, v.z, q.z); q.w = fmaf(v.w, v.w, q.w);
    }
    ss[t] = s; qq[t] = q;
    __syncthreads();

    if (t < 16) {
        float4 S = make_float4(0,0,0,0), Q = make_float4(0,0,0,0);
        #pragma unroll
        for (int j = 0; j < 16; j++) {
            float4 a = ss[j*16 + t];
            float4 b = qq[j*16 + t];
            S.x += a.x; S.y += a.y; S.z += a.z; S.w += a.w;
            Q.x += b.x; Q.y += b.y; Q.z += b.z; Q.w += b.w;
        }
        atomicAdd(&g_stats[t*4+0], S.x); atomicAdd(&g_stats[t*4+1], S.y);
        atomicAdd(&g_stats[t*4+2], S.z); atomicAdd(&g_stats[t*4+3], S.w);
        atomicAdd(&g_stats[COUT + t*4+0], Q.x); atomicAdd(&g_stats[COUT + t*4+1], Q.y);
        atomicAdd(&g_stats[COUT + t*4+2], Q.z); atomicAdd(&g_stats[COUT + t*4+3], Q.w);
    }
}

// ---------------------------------------------------------------- finalize
__global__ void finalize_kernel(const float* __restrict__ gamma,
                                const float* __restrict__ beta)
{
    int d = threadIdx.x;
    if (d < COUT) {
        float inv_n = 1.0f / (float)NVOX;
        float mean  = g_stats[d] * inv_n;
        float var   = g_stats[COUT + d] * inv_n - mean*mean;
        float inv   = rsqrtf(var + 1e-5f);
        float sc    = gamma[d] * inv;
        g_scale[d]  = sc;
        g_shift[d]  = beta[d] - mean*sc;
    }
}

// ---------------------------------------------------------------- normalize
__global__ __launch_bounds__(256)
void norm_kernel(float* __restrict__ out)
{
    __shared__ float sc[COUT], sh[COUT];
    int t = threadIdx.x;
    if (t < COUT) { sc[t] = g_scale[t]; sh[t] = g_shift[t]; }
    __syncthreads();

    const int total4 = NVOX*COUT/4;
    float4* o4 = (float4*)out;
    for (int i = blockIdx.x*blockDim.x + t; i < total4; i += gridDim.x*blockDim.x) {
        float4 v = o4[i];
        int bd = (i*4) & (COUT-1);
        v.x = fmaxf(fmaf(v.x, sc[bd+0], sh[bd+0]), 0.f);
        v.y = fmaxf(fmaf(v.y, sc[bd+1], sh[bd+1]), 0.f);
        v.z = fmaxf(fmaf(v.z, sc[bd+2], sh[bd+2]), 0.f);
        v.w = fmaxf(fmaf(v.w, sc[bd+3], sh[bd+3]), 0.f);
        o4[i] = v;
    }
}

// ---------------------------------------------------------------- launch
extern "C" void kernel_launch(void* const* d_in, const int* in_sizes, int n_in,
                              void* d_out, int out_size)
{
    const float* features = (const float*)d_in[0];  // [150000,32]
    const float* weight   = (const float*)d_in[1];  // [27,32,64]
    const float* gamma    = (const float*)d_in[2];  // [64]
    const float* beta     = (const float*)d_in[3];  // [64]
    const int*   nbr      = (const int*)  d_in[4];  // [27,150000]
    float* out = (float*)d_out;                     // [150000,64]

    zero_kernel<<<1, 128>>>();
    compact_kernel<<<dim3((NVOX + 255)/256, 26), 256>>>(nbr);
    center_gemm_kernel<<<1184, 256>>>(features, weight, out);
    scatter_kernel<<<dim3(24, 26), 256>>>(features, weight, out);
    stats_kernel<<<592, 256>>>(out);
    finalize_kernel<<<1, COUT>>>(gamma, beta);
    norm_kernel<<<1480, 256>>>(out);
}

// round 4
// speedup vs baseline: 6.7719x; 1.6410x over previous
#include <cuda_runtime.h>

#define NVOX    150000
#define CIN     32
#define COUT    64
#define KCENTER 13

__device__ float g_stats[2*COUT];   // [0:64) sum, [64:128) sumsq
__device__ float g_scale[COUT];
__device__ float g_shift[COUT];

// ---------------------------------------------------------------- f32x2 helpers
__device__ __forceinline__ unsigned long long dup2(float x) {
    unsigned long long r; asm("mov.b64 %0, {%1, %1};" : "=l"(r) : "f"(x)); return r;
}
__device__ __forceinline__ unsigned long long pack2(float x, float y) {
    unsigned long long r; asm("mov.b64 %0, {%1, %2};" : "=l"(r) : "f"(x), "f"(y)); return r;
}
__device__ __forceinline__ void unpack2(unsigned long long v, float& x, float& y) {
    asm("mov.b64 {%0, %1}, %2;" : "=f"(x), "=f"(y) : "l"(v));
}
__device__ __forceinline__ void ffma2(unsigned long long& acc,
                                      unsigned long long a, unsigned long long b) {
    asm("fma.rn.f32x2 %0, %1, %2, %0;" : "+l"(acc) : "l"(a), "l"(b));
}
__device__ __forceinline__ unsigned long long add2(unsigned long long a, unsigned long long b) {
    unsigned long long r; asm("add.rn.f32x2 %0, %1, %2;" : "=l"(r) : "l"(a), "l"(b)); return r;
}

// ---------------------------------------------------------------- zero
__global__ void zero_kernel() {
    int t = threadIdx.x;
    if (t < 2*COUT) g_stats[t] = 0.f;
}

// ---------------------------------------------------------------- fused conv + stats
// Warp handles 32 consecutive voxels. Validity mask for the 26 non-center
// offsets is built with coalesced lane-parallel loads; each voxel's full
// output row (center + extras) is computed in-warp, stored once, and
// per-channel sums/sumsqs are accumulated locally -> block reduce -> RED.
#define CW 4   // warps per block
__global__ __launch_bounds__(32*CW)
void conv_fused_kernel(const float* __restrict__ features,
                       const float* __restrict__ weight,
                       const int*   __restrict__ nbr,
                       float* __restrict__ out)
{
    const int lane = threadIdx.x & 31;
    const int warp = threadIdx.x >> 5;
    const int d0   = lane * 2;

    const int chunk = blockIdx.x * CW + warp;   // 32-voxel chunk id
    const int n0    = chunk * 32;

    // validity mask for this lane's voxel (bit j = offset j valid, j skips center)
    unsigned m = 0;
    {
        const int nl = n0 + lane;
        const bool live = nl < NVOX;
        #pragma unroll
        for (int j = 0; j < 26; j++) {
            int k = j + (j >= KCENTER);
            int v = live ? __ldg(&nbr[k*NVOX + nl]) : -1;
            m |= (v >= 0) ? (1u << j) : 0u;
        }
    }

    // center weights in registers: W13[c][d0:d0+2]
    unsigned long long w[CIN];
    {
        const float* wk = weight + KCENTER*CIN*COUT;
        #pragma unroll
        for (int c = 0; c < CIN; c++) {
            float2 wv = __ldg((const float2*)(wk + c*COUT + d0));
            w[c] = pack2(wv.x, wv.y);
        }
    }

    unsigned long long s = 0ull, q = 0ull;   // packed (d0,d0+1) sum / sumsq

    const int nv = (n0 < NVOX) ? min(32, NVOX - n0) : 0;
    for (int i = 0; i < nv; i++) {
        const int n = n0 + i;
        unsigned mi = __shfl_sync(0xffffffffu, m, i);

        // center contribution (idx == n for the center offset)
        const float4* f4 = (const float4*)(features + (size_t)n * CIN);
        unsigned long long accA = 0ull, accB = 0ull;
        #pragma unroll
        for (int j = 0; j < 8; j++) {
            float4 v = f4[j];                  // broadcast LDG.128
            ffma2(accA, dup2(v.x), w[4*j+0]);
            ffma2(accB, dup2(v.y), w[4*j+1]);
            ffma2(accA, dup2(v.z), w[4*j+2]);
            ffma2(accB, dup2(v.w), w[4*j+3]);
        }

        // rare extras (~0.23 per voxel on average)
        while (mi) {
            int j = __ffs(mi) - 1; mi &= mi - 1;
            int k = j + (j >= KCENTER);
            int idx = __ldg(&nbr[k*NVOX + n]);                 // L1-hot broadcast
            const float* wk = weight + k*CIN*COUT;
            const float4* g4 = (const float4*)(features + (size_t)idx * CIN);
            float4 v0 = g4[0], v1 = g4[1], v2 = g4[2], v3 = g4[3];
            float4 v4 = g4[4], v5 = g4[5], v6 = g4[6], v7 = g4[7];
            const float4 vv[8] = {v0,v1,v2,v3,v4,v5,v6,v7};
            #pragma unroll
            for (int jj = 0; jj < 8; jj++) {
                float2 w0 = __ldg((const float2*)(wk + (4*jj+0)*COUT + d0));
                float2 w1 = __ldg((const float2*)(wk + (4*jj+1)*COUT + d0));
                float2 w2 = __ldg((const float2*)(wk + (4*jj+2)*COUT + d0));
                float2 w3 = __ldg((const float2*)(wk + (4*jj+3)*COUT + d0));
                ffma2(accA, dup2(vv[jj].x), pack2(w0.x, w0.y));
                ffma2(accB, dup2(vv[jj].y), pack2(w1.x, w1.y));
                ffma2(accA, dup2(vv[jj].z), pack2(w2.x, w2.y));
                ffma2(accB, dup2(vv[jj].w), pack2(w3.x, w3.y));
            }
        }

        unsigned long long acc = add2(accA, accB);
        float a0, a1; unpack2(acc, a0, a1);
        *(float2*)(out + (size_t)n*COUT + d0) = make_float2(a0, a1);

        s = add2(s, acc);
        ffma2(q, acc, acc);
    }

    // block reduce: per-lane packed stats across CW warps
    __shared__ float4 red[CW*32];
    float s0, s1, q0, q1;
    unpack2(s, s0, s1); unpack2(q, q0, q1);
    red[warp*32 + lane] = make_float4(s0, s1, q0, q1);
    __syncthreads();

    if (threadIdx.x < 32) {
        float4 a = red[threadIdx.x];
        #pragma unroll
        for (int ww = 1; ww < CW; ww++) {
            float4 b = red[ww*32 + threadIdx.x];
            a.x += b.x; a.y += b.y; a.z += b.z; a.w += b.w;
        }
        atomicAdd(&g_stats[2*threadIdx.x + 0],        a.x);
        atomicAdd(&g_stats[2*threadIdx.x + 1],        a.y);
        atomicAdd(&g_stats[COUT + 2*threadIdx.x + 0], a.z);
        atomicAdd(&g_stats[COUT + 2*threadIdx.x + 1], a.w);
    }
}

// ---------------------------------------------------------------- finalize
__global__ void finalize_kernel(const float* __restrict__ gamma,
                                const float* __restrict__ beta)
{
    int d = threadIdx.x;
    if (d < COUT) {
        float inv_n = 1.0f / (float)NVOX;
        float mean  = g_stats[d] * inv_n;
        float var   = g_stats[COUT + d] * inv_n - mean*mean;
        float inv   = rsqrtf(var + 1e-5f);
        float sc    = gamma[d] * inv;
        g_scale[d]  = sc;
        g_shift[d]  = beta[d] - mean*sc;
    }
}

// ---------------------------------------------------------------- normalize
__global__ __launch_bounds__(256)
void norm_kernel(float* __restrict__ out)
{
    __shared__ float sc[COUT], sh[COUT];
    int t = threadIdx.x;
    if (t < COUT) { sc[t] = g_scale[t]; sh[t] = g_shift[t]; }
    __syncthreads();

    const int total4 = NVOX*COUT/4;
    float4* o4 = (float4*)out;
    for (int i = blockIdx.x*blockDim.x + t; i < total4; i += gridDim.x*blockDim.x) {
        float4 v = o4[i];
        int bd = (i*4) & (COUT-1);
        v.x = fmaxf(fmaf(v.x, sc[bd+0], sh[bd+0]), 0.f);
        v.y = fmaxf(fmaf(v.y, sc[bd+1], sh[bd+1]), 0.f);
        v.z = fmaxf(fmaf(v.z, sc[bd+2], sh[bd+2]), 0.f);
        v.w = fmaxf(fmaf(v.w, sc[bd+3], sh[bd+3]), 0.f);
        o4[i] = v;
    }
}

// ---------------------------------------------------------------- launch
extern "C" void kernel_launch(void* const* d_in, const int* in_sizes, int n_in,
                              void* d_out, int out_size)
{
    const float* features = (const float*)d_in[0];  // [150000,32]
    const float* weight   = (const float*)d_in[1];  // [27,32,64]
    const float* gamma    = (const float*)d_in[2];  // [64]
    const float* beta     = (const float*)d_in[3];  // [64]
    const int*   nbr      = (const int*)  d_in[4];  // [27,150000]
    float* out = (float*)d_out;                     // [150000,64]

    const int nchunks = (NVOX + 31) / 32;           // 4688
    const int blocks  = (nchunks + CW - 1) / CW;    // 1172

    zero_kernel<<<1, 128>>>();
    conv_fused_kernel<<<blocks, 32*CW>>>(features, weight, nbr, out);
    finalize_kernel<<<1, COUT>>>(gamma, beta);
    norm_kernel<<<1480, 256>>>(out);
}